// round 8
// baseline (speedup 1.0000x reference)
#include <cuda_runtime.h>
#include <cstddef>

#define BDIM 1024
#define SDIM 258
#define IDIM 512
#define HDIM 512
#define G4   (4*HDIM)   // 2048

// ---------------- scratch (device globals; no allocations allowed) ----------
__device__ __align__(16) float g_Acat[(size_t)BDIM*(IDIM+HDIM)];   // [char | h_gather]
__device__ __align__(16) float g_gates_r[(size_t)BDIM*G4];
__device__ __align__(16) float g_gates_l[(size_t)BDIM*G4];
__device__ __align__(16) float g_hlcat[(size_t)BDIM*(2*HDIM)];     // [h_r | h_l]
__device__ __align__(16) float g_hr[(size_t)BDIM*HDIM];
__device__ __align__(16) float g_cr[(size_t)BDIM*HDIM];

__device__ __forceinline__ float sigf(float x) { return 1.0f / (1.0f + expf(-x)); }

// ------------- bulk copy, PERSISTENT small grid (co-resident w/ GEMM) -------
__global__ void __launch_bounds__(256)
copy_stacks_kernel(const float4* __restrict__ sh,
                   const float4* __restrict__ sc,
                   float4* __restrict__ dh,
                   float4* __restrict__ dc,
                   size_t n4) {
    size_t stride = (size_t)gridDim.x * blockDim.x;
    size_t i = (size_t)blockIdx.x * blockDim.x + threadIdx.x;
    // unroll-4: 8 independent loads in flight before stores
    for (; i + 3 * stride < n4; i += 4 * stride) {
        float4 a0 = sh[i];
        float4 a1 = sh[i + stride];
        float4 a2 = sh[i + 2 * stride];
        float4 a3 = sh[i + 3 * stride];
        float4 b0 = sc[i];
        float4 b1 = sc[i + stride];
        float4 b2 = sc[i + 2 * stride];
        float4 b3 = sc[i + 3 * stride];
        dh[i] = a0;               dh[i + stride] = a1;
        dh[i + 2 * stride] = a2;  dh[i + 3 * stride] = a3;
        dc[i] = b0;               dc[i + stride] = b1;
        dc[i + 2 * stride] = b2;  dc[i + 3 * stride] = b3;
    }
    for (; i < n4; i += stride) {
        dh[i] = sh[i];
        dc[i] = sc[i];
    }
}

// ---------------- gather A = [char | stack_hidden[b, pos[b]]] ---------------
__global__ void gather_kernel(const float* __restrict__ ch,
                              const float* __restrict__ sh,
                              const int* __restrict__ pos) {
    int idx = blockIdx.x * blockDim.x + threadIdx.x;   // over B*H/4
    if (idx >= BDIM * (HDIM / 4)) return;
    int b = idx / (HDIM / 4);
    int q = idx % (HDIM / 4);
    const float4* chv = (const float4*)ch;
    const float4* shv = (const float4*)sh;
    float4* Ac = (float4*)g_Acat;
    int p = pos[b];
    float4 cv = chv[(size_t)b * (IDIM / 4) + q];
    float4 hv = shv[((size_t)b * SDIM + p) * (HDIM / 4) + q];
    Ac[(size_t)b * 256 + q]       = cv;
    Ac[(size_t)b * 256 + 128 + q] = hv;
}

// ---------------- tiled fp32 GEMM: C = A @ W^T + b1(+b2), opt tanh ----------
#define BM 128
#define BN 64
#define BK 16
#define TM 8
#define TN 4

__global__ __launch_bounds__(256)
void gemm_ws_kernel(const float* __restrict__ A,
                    const float* __restrict__ W1,
                    const float* __restrict__ W2,
                    int K1, int K,
                    const float* __restrict__ b1,
                    const float* __restrict__ b2,
                    float* __restrict__ C,
                    int N, int act) {
    __shared__ __align__(16) float As[BK][BM];
    __shared__ __align__(16) float Bs[BK][BN];

    int tid = threadIdx.x;
    int tx = tid & 15;
    int ty = tid >> 4;
    int block_m = blockIdx.y * BM;
    int block_n = blockIdx.x * BN;

    float acc[TM][TN];
    #pragma unroll
    for (int i = 0; i < TM; i++)
        #pragma unroll
        for (int j = 0; j < TN; j++) acc[i][j] = 0.0f;

    for (int k0 = 0; k0 < K; k0 += BK) {
        #pragma unroll
        for (int it = 0; it < 2; it++) {
            int li = tid + it * 256;
            int m  = li >> 2;
            int kq = (li & 3) << 2;
            float4 v = *reinterpret_cast<const float4*>(
                &A[(size_t)(block_m + m) * K + k0 + kq]);
            As[kq + 0][m] = v.x; As[kq + 1][m] = v.y;
            As[kq + 2][m] = v.z; As[kq + 3][m] = v.w;
        }
        {
            int li = tid;
            int n  = li >> 2;
            int kq = (li & 3) << 2;
            int kk = k0 + kq;
            const float* Wp; int kw, Kw;
            if (kk < K1) { Wp = W1; kw = kk;       Kw = K1;     }
            else         { Wp = W2; kw = kk - K1;  Kw = K - K1; }
            float4 v = *reinterpret_cast<const float4*>(
                &Wp[(size_t)(block_n + n) * Kw + kw]);
            Bs[kq + 0][n] = v.x; Bs[kq + 1][n] = v.y;
            Bs[kq + 2][n] = v.z; Bs[kq + 3][n] = v.w;
        }
        __syncthreads();

        #pragma unroll
        for (int kk = 0; kk < BK; kk++) {
            float4 a0 = *reinterpret_cast<const float4*>(&As[kk][ty * TM]);
            float4 a1 = *reinterpret_cast<const float4*>(&As[kk][ty * TM + 4]);
            float4 bv = *reinterpret_cast<const float4*>(&Bs[kk][tx * TN]);
            float a[TM] = {a0.x, a0.y, a0.z, a0.w, a1.x, a1.y, a1.z, a1.w};
            float bcol[TN] = {bv.x, bv.y, bv.z, bv.w};
            #pragma unroll
            for (int i = 0; i < TM; i++)
                #pragma unroll
                for (int j = 0; j < TN; j++)
                    acc[i][j] += a[i] * bcol[j];
        }
        __syncthreads();
    }

    float bb[TN];
    #pragma unroll
    for (int j = 0; j < TN; j++) {
        int n = block_n + tx * TN + j;
        float bsum = b1 ? b1[n] : 0.0f;
        if (b2) bsum += b2[n];
        bb[j] = bsum;
    }
    #pragma unroll
    for (int i = 0; i < TM; i++) {
        int m = block_m + ty * TM + i;
        float r[TN];
        #pragma unroll
        for (int j = 0; j < TN; j++) {
            float x = acc[i][j] + bb[j];
            if (act == 1) x = tanhf(x);
            r[j] = x;
        }
        *reinterpret_cast<float4*>(&C[(size_t)m * N + block_n + tx * TN]) =
            make_float4(r[0], r[1], r[2], r[3]);
    }
}

// ---------------- LSTM elementwise (NO scatter — overlappable) --------------
__global__ void lstm_elem_kernel(const float* __restrict__ stack_cell,
                                 const int* __restrict__ pos) {
    int idx = blockIdx.x * blockDim.x + threadIdx.x;
    if (idx >= BDIM * HDIM) return;
    int b = idx / HDIM;
    int j = idx - b * HDIM;

    const float* gr = g_gates_r + (size_t)b * G4;
    const float* gl = g_gates_l + (size_t)b * G4;

    float ig = gr[j];
    float fg = gr[HDIM + j];
    float gg = gr[2 * HDIM + j];
    float og = gr[3 * HDIM + j];

    int p = pos[b];
    float cprev = stack_cell[((size_t)b * SDIM + p) * HDIM + j];
    float cr = sigf(fg) * cprev + sigf(ig) * tanhf(gg);
    float hr = sigf(og) * tanhf(cr);

    float cl = sigf(gl[j]) * tanhf(gl[2 * HDIM + j]);
    float hl = sigf(gl[3 * HDIM + j]) * tanhf(cl);

    g_hlcat[(size_t)b * (2 * HDIM) + j]        = hr;
    g_hlcat[(size_t)b * (2 * HDIM) + HDIM + j] = hl;
    g_hr[idx] = hr;
    g_cr[idx] = cr;
}

// ---------------- scatter h_r/c_r at pos+1 (after copy join) ----------------
__global__ void scatter_kernel(const int* __restrict__ pos,
                               float4* __restrict__ out_h,
                               float4* __restrict__ out_c) {
    int idx = blockIdx.x * blockDim.x + threadIdx.x;   // over B*H/4
    if (idx >= BDIM * (HDIM / 4)) return;
    int b = idx / (HDIM / 4);
    int q = idx - b * (HDIM / 4);
    const float4* hr = (const float4*)g_hr;
    const float4* cr = (const float4*)g_cr;
    int p = pos[b] + 1;
    size_t off = ((size_t)b * SDIM + p) * (HDIM / 4) + q;
    out_h[off] = hr[(size_t)b * (HDIM / 4) + q];
    out_c[off] = cr[(size_t)b * (HDIM / 4) + q];
}

// ---------------------------------------------------------------------------
extern "C" void kernel_launch(void* const* d_in, const int* in_sizes, int n_in,
                              void* d_out, int out_size) {
    const float* ch     = (const float*)d_in[0];
    const float* sh     = (const float*)d_in[1];
    const float* sc     = (const float*)d_in[2];
    const int*   pos    = (const int*)d_in[3];
    const float* W_ih_r = (const float*)d_in[4];
    const float* W_hh_r = (const float*)d_in[5];
    const float* b_ih_r = (const float*)d_in[6];
    const float* b_hh_r = (const float*)d_in[7];
    const float* W_ih_l = (const float*)d_in[8];
    const float* W_hh_l = (const float*)d_in[9];   (void)W_hh_l;  // h=0, unused
    const float* b_ih_l = (const float*)d_in[10];
    const float* b_hh_l = (const float*)d_in[11];
    const float* W_comp = (const float*)d_in[12];
    const float* b_comp = (const float*)d_in[13];

    float* out      = (float*)d_out;
    float* out_sub  = out;                                    // (B, H)
    float* out_h    = out + (size_t)BDIM * HDIM;              // (B, S, H)
    float* out_c    = out_h + (size_t)BDIM * SDIM * HDIM;     // (B, S, H)

    static cudaStream_t s_copy = nullptr;
    static cudaEvent_t ev_fork = nullptr, ev_copy_done = nullptr;
    if (s_copy == nullptr) {
        cudaStreamCreateWithFlags(&s_copy, cudaStreamNonBlocking);
        cudaEventCreateWithFlags(&ev_fork, cudaEventDisableTiming);
        cudaEventCreateWithFlags(&ev_copy_done, cudaEventDisableTiming);
    }

    float* gAcat;    cudaGetSymbolAddress((void**)&gAcat,    g_Acat);
    float* gGatesR;  cudaGetSymbolAddress((void**)&gGatesR,  g_gates_r);
    float* gGatesL;  cudaGetSymbolAddress((void**)&gGatesL,  g_gates_l);
    float* gHlcat;   cudaGetSymbolAddress((void**)&gHlcat,   g_hlcat);

    // ---- fork: PERSISTENT copy kernel on side stream (2 blocks/SM; leaves
    //      registers/warp-slots free so GEMM blocks co-reside and overlap)
    cudaEventRecord(ev_fork, 0);
    cudaStreamWaitEvent(s_copy, ev_fork, 0);
    {
        size_t n4 = (size_t)BDIM * SDIM * HDIM / 4;   // 33,816,576
        copy_stacks_kernel<<<296, 256, 0, s_copy>>>(
            (const float4*)sh, (const float4*)sc,
            (float4*)out_h, (float4*)out_c, n4);
    }
    cudaEventRecord(ev_copy_done, s_copy);

    // ---- main stream: gather -> GEMMs -> elementwise -> compose
    {
        int total = BDIM * (HDIM / 4);
        gather_kernel<<<(total + 255) / 256, 256>>>(ch, sh, pos);
    }
    {
        dim3 grid(G4 / BN, BDIM / BM);   // (32, 8)
        gemm_ws_kernel<<<grid, 256>>>(gAcat, W_ih_r, W_hh_r, IDIM, IDIM + HDIM,
                                      b_ih_r, b_hh_r, gGatesR, G4, 0);
    }
    {
        dim3 grid(G4 / BN, BDIM / BM);
        gemm_ws_kernel<<<grid, 256>>>(ch, W_ih_l, nullptr, IDIM, IDIM,
                                      b_ih_l, b_hh_l, gGatesL, G4, 0);
    }
    {
        int total = BDIM * HDIM;
        lstm_elem_kernel<<<(total + 255) / 256, 256>>>(sc, pos);
    }
    {
        dim3 grid(HDIM / BN, BDIM / BM);  // (8, 8)
        gemm_ws_kernel<<<grid, 256>>>(gHlcat, W_comp, nullptr, 2 * HDIM, 2 * HDIM,
                                      b_comp, nullptr, out_sub, HDIM, 1);
    }

    // ---- join: scatter (h_r, c_r) at pos+1 after the bulk copy
    cudaStreamWaitEvent(0, ev_copy_done, 0);
    {
        int total = BDIM * (HDIM / 4);
        scatter_kernel<<<(total + 255) / 256, 256>>>(pos, (float4*)out_h,
                                                     (float4*)out_c);
    }
}

// round 9
// speedup vs baseline: 1.1319x; 1.1319x over previous
#include <cuda_runtime.h>
#include <cstddef>

#define BDIM 1024
#define SDIM 258
#define IDIM 512
#define HDIM 512
#define G4   (4*HDIM)   // 2048

// ---------------- scratch (device globals; no allocations allowed) ----------
__device__ __align__(16) float g_Acat[(size_t)BDIM*(IDIM+HDIM)];   // [char | h_gather]
__device__ __align__(16) float g_gates_r[(size_t)BDIM*G4];
__device__ __align__(16) float g_gates_l[(size_t)BDIM*G4];
__device__ __align__(16) float g_hlcat[(size_t)BDIM*(2*HDIM)];     // [h_r | h_l]
__device__ __align__(16) float g_hr[(size_t)BDIM*HDIM];
__device__ __align__(16) float g_cr[(size_t)BDIM*HDIM];

__device__ __forceinline__ float sigf(float x) { return 1.0f / (1.0f + expf(-x)); }

// ---------------- generic streaming copy (remainder) ------------------------
__global__ void __launch_bounds__(256)
copy1_kernel(const float4* __restrict__ s, float4* __restrict__ d, size_t n) {
    size_t stride = (size_t)gridDim.x * blockDim.x;
    size_t i = (size_t)blockIdx.x * blockDim.x + threadIdx.x;
    for (; i + 3 * stride < n; i += 4 * stride) {
        float4 v0 = s[i];
        float4 v1 = s[i + stride];
        float4 v2 = s[i + 2 * stride];
        float4 v3 = s[i + 3 * stride];
        d[i] = v0;               d[i + stride] = v1;
        d[i + 2 * stride] = v2;  d[i + 3 * stride] = v3;
    }
    for (; i < n; i += stride) d[i] = s[i];
}

// ---------------- gather A = [char | stack_hidden[b, pos[b]]] ---------------
__global__ void gather_kernel(const float* __restrict__ ch,
                              const float* __restrict__ sh,
                              const int* __restrict__ pos) {
    int idx = blockIdx.x * blockDim.x + threadIdx.x;   // over B*H/4
    if (idx >= BDIM * (HDIM / 4)) return;
    int b = idx / (HDIM / 4);
    int q = idx % (HDIM / 4);
    const float4* chv = (const float4*)ch;
    const float4* shv = (const float4*)sh;
    float4* Ac = (float4*)g_Acat;
    int p = pos[b];
    float4 cv = chv[(size_t)b * (IDIM / 4) + q];
    float4 hv = shv[((size_t)b * SDIM + p) * (HDIM / 4) + q];
    Ac[(size_t)b * 256 + q]       = cv;
    Ac[(size_t)b * 256 + 128 + q] = hv;
}

// ------- tiled fp32 GEMM with FUSED stack-copy slice ------------------------
// C = A @ W^T + b1(+b2), opt tanh.  W(n,k) = k<K1 ? W1 : W2 (split source).
// Copy: unified unit space u in [0, 2*n4): u<n4 -> h-stack, else c-stack.
// Each block/thread/k-iter moves CPY float4 units from its assigned range.
#define BM 128
#define BN 64
#define BK 16
#define TM 8
#define TN 4
#define CPY 4

__global__ __launch_bounds__(256)
void gemm_ws_kernel(const float* __restrict__ A,
                    const float* __restrict__ W1,
                    const float* __restrict__ W2,
                    int K1, int K,
                    const float* __restrict__ b1,
                    const float* __restrict__ b2,
                    float* __restrict__ C,
                    int N, int act,
                    const float4* __restrict__ csh,
                    const float4* __restrict__ csc,
                    float4* __restrict__ cdh,
                    float4* __restrict__ cdc,
                    size_t c_n4, size_t c_off, size_t c_end) {
    __shared__ __align__(16) float As[BK][BM];
    __shared__ __align__(16) float Bs[BK][BN];

    int tid = threadIdx.x;
    int tx = tid & 15;
    int ty = tid >> 4;
    int block_m = blockIdx.y * BM;
    int block_n = blockIdx.x * BN;
    size_t nblk = (size_t)gridDim.x * gridDim.y;
    size_t bid  = (size_t)blockIdx.y * gridDim.x + blockIdx.x;

    float acc[TM][TN];
    #pragma unroll
    for (int i = 0; i < TM; i++)
        #pragma unroll
        for (int j = 0; j < TN; j++) acc[i][j] = 0.0f;

    int k_it = 0;
    for (int k0 = 0; k0 < K; k0 += BK, k_it++) {
        // ---- fused copy: issue loads early (latency hidden by FMA loop) ----
        float4 cv[CPY];
        size_t cu[CPY];
        bool   cok[CPY];
        #pragma unroll
        for (int c = 0; c < CPY; c++) {
            size_t u = c_off + (((size_t)(k_it * CPY + c)) * nblk + bid) * 256 + tid;
            cok[c] = (u < c_end);
            cu[c] = u;
            if (cok[c]) cv[c] = (u < c_n4) ? csh[u] : csc[u - c_n4];
        }

        // ---- GEMM tile loads ----
        #pragma unroll
        for (int it = 0; it < 2; it++) {
            int li = tid + it * 256;
            int m  = li >> 2;
            int kq = (li & 3) << 2;
            float4 v = *reinterpret_cast<const float4*>(
                &A[(size_t)(block_m + m) * K + k0 + kq]);
            As[kq + 0][m] = v.x; As[kq + 1][m] = v.y;
            As[kq + 2][m] = v.z; As[kq + 3][m] = v.w;
        }
        {
            int li = tid;
            int n  = li >> 2;
            int kq = (li & 3) << 2;
            int kk = k0 + kq;
            const float* Wp; int kw, Kw;
            if (kk < K1) { Wp = W1; kw = kk;       Kw = K1;     }
            else         { Wp = W2; kw = kk - K1;  Kw = K - K1; }
            float4 v = *reinterpret_cast<const float4*>(
                &Wp[(size_t)(block_n + n) * Kw + kw]);
            Bs[kq + 0][n] = v.x; Bs[kq + 1][n] = v.y;
            Bs[kq + 2][n] = v.z; Bs[kq + 3][n] = v.w;
        }
        __syncthreads();

        #pragma unroll
        for (int kk = 0; kk < BK; kk++) {
            float4 a0 = *reinterpret_cast<const float4*>(&As[kk][ty * TM]);
            float4 a1 = *reinterpret_cast<const float4*>(&As[kk][ty * TM + 4]);
            float4 bv = *reinterpret_cast<const float4*>(&Bs[kk][tx * TN]);
            float a[TM] = {a0.x, a0.y, a0.z, a0.w, a1.x, a1.y, a1.z, a1.w};
            float bcol[TN] = {bv.x, bv.y, bv.z, bv.w};
            #pragma unroll
            for (int i = 0; i < TM; i++)
                #pragma unroll
                for (int j = 0; j < TN; j++)
                    acc[i][j] += a[i] * bcol[j];
        }
        __syncthreads();

        // ---- fused copy: dependent stores (loads completed during FMAs) ----
        #pragma unroll
        for (int c = 0; c < CPY; c++) {
            if (cok[c]) {
                if (cu[c] < c_n4) cdh[cu[c]] = cv[c];
                else              cdc[cu[c] - c_n4] = cv[c];
            }
        }
    }

    float bb[TN];
    #pragma unroll
    for (int j = 0; j < TN; j++) {
        int n = block_n + tx * TN + j;
        float bsum = b1 ? b1[n] : 0.0f;
        if (b2) bsum += b2[n];
        bb[j] = bsum;
    }
    #pragma unroll
    for (int i = 0; i < TM; i++) {
        int m = block_m + ty * TM + i;
        float r[TN];
        #pragma unroll
        for (int j = 0; j < TN; j++) {
            float x = acc[i][j] + bb[j];
            if (act == 1) x = tanhf(x);
            r[j] = x;
        }
        *reinterpret_cast<float4*>(&C[(size_t)m * N + block_n + tx * TN]) =
            make_float4(r[0], r[1], r[2], r[3]);
    }
}

// ---------------- LSTM elementwise ------------------------------------------
__global__ void lstm_elem_kernel(const float* __restrict__ stack_cell,
                                 const int* __restrict__ pos) {
    int idx = blockIdx.x * blockDim.x + threadIdx.x;
    if (idx >= BDIM * HDIM) return;
    int b = idx / HDIM;
    int j = idx - b * HDIM;

    const float* gr = g_gates_r + (size_t)b * G4;
    const float* gl = g_gates_l + (size_t)b * G4;

    float ig = gr[j];
    float fg = gr[HDIM + j];
    float gg = gr[2 * HDIM + j];
    float og = gr[3 * HDIM + j];

    int p = pos[b];
    float cprev = stack_cell[((size_t)b * SDIM + p) * HDIM + j];
    float cr = sigf(fg) * cprev + sigf(ig) * tanhf(gg);
    float hr = sigf(og) * tanhf(cr);

    float cl = sigf(gl[j]) * tanhf(gl[2 * HDIM + j]);
    float hl = sigf(gl[3 * HDIM + j]) * tanhf(cl);

    g_hlcat[(size_t)b * (2 * HDIM) + j]        = hr;
    g_hlcat[(size_t)b * (2 * HDIM) + HDIM + j] = hl;
    g_hr[idx] = hr;
    g_cr[idx] = cr;
}

// ---------------- scatter h_r/c_r at pos+1 (runs last) ----------------------
__global__ void scatter_kernel(const int* __restrict__ pos,
                               float4* __restrict__ out_h,
                               float4* __restrict__ out_c) {
    int idx = blockIdx.x * blockDim.x + threadIdx.x;   // over B*H/4
    if (idx >= BDIM * (HDIM / 4)) return;
    int b = idx / (HDIM / 4);
    int q = idx - b * (HDIM / 4);
    const float4* hr = (const float4*)g_hr;
    const float4* cr = (const float4*)g_cr;
    int p = pos[b] + 1;
    size_t off = ((size_t)b * SDIM + p) * (HDIM / 4) + q;
    out_h[off] = hr[(size_t)b * (HDIM / 4) + q];
    out_c[off] = cr[(size_t)b * (HDIM / 4) + q];
}

// ---------------------------------------------------------------------------
extern "C" void kernel_launch(void* const* d_in, const int* in_sizes, int n_in,
                              void* d_out, int out_size) {
    const float* ch     = (const float*)d_in[0];
    const float* sh     = (const float*)d_in[1];
    const float* sc     = (const float*)d_in[2];
    const int*   pos    = (const int*)d_in[3];
    const float* W_ih_r = (const float*)d_in[4];
    const float* W_hh_r = (const float*)d_in[5];
    const float* b_ih_r = (const float*)d_in[6];
    const float* b_hh_r = (const float*)d_in[7];
    const float* W_ih_l = (const float*)d_in[8];
    const float* W_hh_l = (const float*)d_in[9];   (void)W_hh_l;  // h=0, unused
    const float* b_ih_l = (const float*)d_in[10];
    const float* b_hh_l = (const float*)d_in[11];
    const float* W_comp = (const float*)d_in[12];
    const float* b_comp = (const float*)d_in[13];

    float* out      = (float*)d_out;
    float* out_sub  = out;                                    // (B, H)
    float* out_h    = out + (size_t)BDIM * HDIM;              // (B, S, H)
    float* out_c    = out_h + (size_t)BDIM * SDIM * HDIM;     // (B, S, H)

    float* gAcat;    cudaGetSymbolAddress((void**)&gAcat,    g_Acat);
    float* gGatesR;  cudaGetSymbolAddress((void**)&gGatesR,  g_gates_r);
    float* gGatesL;  cudaGetSymbolAddress((void**)&gGatesL,  g_gates_l);
    float* gHlcat;   cudaGetSymbolAddress((void**)&gHlcat,   g_hlcat);

    const size_t n4 = (size_t)BDIM * SDIM * HDIM / 4;   // 33,816,576 float4/stack
    const float4* csh = (const float4*)sh;
    const float4* csc = (const float4*)sc;
    float4* cdh = (float4*)out_h;
    float4* cdc = (float4*)out_c;

    // static copy-slice assignment (float4 units over unified [0, 2*n4))
    const size_t cap_r = (size_t)((IDIM + HDIM) / BK) * CPY * 256 * 256; // 16,777,216
    const size_t cap_l = (size_t)(IDIM / BK)          * CPY * 256 * 256; //  8,388,608
    const size_t cap_c = (size_t)((2 * HDIM) / BK)    * CPY * 64  * 256; //  4,194,304
    const size_t off_r = 0;
    const size_t off_l = off_r + cap_r;
    const size_t off_c = off_l + cap_l;
    const size_t off_rem = off_c + cap_c;      // 29,360,128

    // ---- serial chain, copy fused into GEMMs ----
    {
        int total = BDIM * (HDIM / 4);
        gather_kernel<<<(total + 255) / 256, 256>>>(ch, sh, pos);
    }
    {
        dim3 grid(G4 / BN, BDIM / BM);   // (32, 8) = 256 blocks
        gemm_ws_kernel<<<grid, 256>>>(gAcat, W_ih_r, W_hh_r, IDIM, IDIM + HDIM,
                                      b_ih_r, b_hh_r, gGatesR, G4, 0,
                                      csh, csc, cdh, cdc, n4, off_r, off_r + cap_r);
    }
    {
        dim3 grid(G4 / BN, BDIM / BM);   // 256 blocks
        gemm_ws_kernel<<<grid, 256>>>(ch, W_ih_l, nullptr, IDIM, IDIM,
                                      b_ih_l, b_hh_l, gGatesL, G4, 0,
                                      csh, csc, cdh, cdc, n4, off_l, off_l + cap_l);
    }
    {
        int total = BDIM * HDIM;
        lstm_elem_kernel<<<(total + 255) / 256, 256>>>(sc, pos);
    }
    {
        dim3 grid(HDIM / BN, BDIM / BM);  // (8, 8) = 64 blocks
        gemm_ws_kernel<<<grid, 256>>>(gHlcat, W_comp, nullptr, 2 * HDIM, 2 * HDIM,
                                      b_comp, nullptr, out_sub, HDIM, 1,
                                      csh, csc, cdh, cdc, n4, off_c, off_c + cap_c);
    }

    // ---- remainder copy: h tail [off_rem, n4) and full c stack ----
    {
        size_t nh = n4 - off_rem;                 // 4,456,448 float4
        int blocks = (int)((nh + 1023) / 1024);
        copy1_kernel<<<blocks, 256>>>(csh + off_rem, cdh + off_rem, nh);
    }
    {
        int blocks = (int)((n4 + 1023) / 1024);
        copy1_kernel<<<blocks, 256>>>(csc, cdc, n4);
    }

    // ---- scatter (h_r, c_r) at pos+1, after all copies ----
    {
        int total = BDIM * (HDIM / 4);
        scatter_kernel<<<(total + 255) / 256, 256>>>(pos, (float4*)out_h,
                                                     (float4*)out_c);
    }
}

// round 13
// speedup vs baseline: 1.4535x; 1.2841x over previous
#include <cuda_runtime.h>
#include <cstddef>

#define BDIM 1024
#define SDIM 258
#define IDIM 512
#define HDIM 512
#define G4   (4*HDIM)   // 2048

#define BM 128
#define BN 64
#define BK 16
#define TM 8
#define TN 4
#define NCPY 148        // copy-role blocks per launch (1 per SM)

// ---------------- scratch (device globals; no allocations allowed) ----------
__device__ __align__(16) float g_gates_r[(size_t)BDIM*G4];
__device__ __align__(16) float g_gates_l[(size_t)BDIM*G4];
__device__ __align__(16) float g_hlcat[(size_t)BDIM*(2*HDIM)];     // [h_r | h_l]
__device__ __align__(16) float g_hr[(size_t)BDIM*HDIM];
__device__ __align__(16) float g_cr[(size_t)BDIM*HDIM];

__device__ __forceinline__ float sigf(float x) { return 1.0f / (1.0f + expf(-x)); }

// ---------------- copy role: stream units of unified space [0, 2*n4) --------
// u < n4 -> h stack, else c stack. Block-interleaved granules, unroll-8.
__device__ __forceinline__ void copy_role(
    int cb, size_t c0, size_t c1, size_t n4,
    const float4* __restrict__ csh, const float4* __restrict__ csc,
    float4* __restrict__ cdh, float4* __restrict__ cdc)
{
    const size_t stride = (size_t)NCPY * 256;
    size_t i = c0 + (size_t)cb * 256 + threadIdx.x;
    for (; i + 7 * stride < c1; i += 8 * stride) {
        float4 v[8];
        #pragma unroll
        for (int j = 0; j < 8; j++) {
            size_t u = i + (size_t)j * stride;
            v[j] = (u < n4) ? csh[u] : csc[u - n4];
        }
        #pragma unroll
        for (int j = 0; j < 8; j++) {
            size_t u = i + (size_t)j * stride;
            if (u < n4) cdh[u] = v[j];
            else        cdc[u - n4] = v[j];
        }
    }
    for (; i < c1; i += stride) {
        if (i < n4) cdh[i] = csh[i];
        else        cdc[i - n4] = csc[i - n4];
    }
}

// ---------------- GEMM tile: C[bm:bm+128, bn:bn+64] = A @ W^T + b (+tanh) ---
// a_mode 0: A0 row-major (M,K).  a_mode 1: A = [char | sh[b, pos[b]]] gather.
// W(n,k) = k<K1 ? W1 : W2.
__device__ __forceinline__ void gemm_tile(
    int block_m, int block_n, int a_mode,
    const float* __restrict__ A0,
    const float* __restrict__ sh, const int* __restrict__ pos,
    const float* __restrict__ W1, const float* __restrict__ W2,
    int K1, int K,
    const float* __restrict__ b1, const float* __restrict__ b2,
    float* __restrict__ C, int N, int act,
    float (*As)[BM], float (*Bs)[BN], int* pos_s)
{
    int tid = threadIdx.x;
    int tx = tid & 15;
    int ty = tid >> 4;

    if (a_mode == 1 && tid < BM) pos_s[tid] = pos[block_m + tid];
    __syncthreads();

    float acc[TM][TN];
    #pragma unroll
    for (int i = 0; i < TM; i++)
        #pragma unroll
        for (int j = 0; j < TN; j++) acc[i][j] = 0.0f;

    for (int k0 = 0; k0 < K; k0 += BK) {
        #pragma unroll
        for (int it = 0; it < 2; it++) {
            int li = tid + it * 256;
            int m  = li >> 2;
            int kq = (li & 3) << 2;
            int mg = block_m + m;
            int kk = k0 + kq;
            const float* src;
            if (a_mode == 0) {
                src = &A0[(size_t)mg * K + kk];
            } else if (kk < IDIM) {
                src = &A0[(size_t)mg * IDIM + kk];
            } else {
                src = &sh[((size_t)mg * SDIM + pos_s[m]) * HDIM + (kk - IDIM)];
            }
            float4 v = *reinterpret_cast<const float4*>(src);
            As[kq + 0][m] = v.x; As[kq + 1][m] = v.y;
            As[kq + 2][m] = v.z; As[kq + 3][m] = v.w;
        }
        {
            int li = tid;
            int n  = li >> 2;
            int kq = (li & 3) << 2;
            int kk = k0 + kq;
            const float* Wp; int kw, Kw;
            if (kk < K1) { Wp = W1; kw = kk;       Kw = K1;     }
            else         { Wp = W2; kw = kk - K1;  Kw = K - K1; }
            float4 v = *reinterpret_cast<const float4*>(
                &Wp[(size_t)(block_n + n) * Kw + kw]);
            Bs[kq + 0][n] = v.x; Bs[kq + 1][n] = v.y;
            Bs[kq + 2][n] = v.z; Bs[kq + 3][n] = v.w;
        }
        __syncthreads();

        #pragma unroll
        for (int kk = 0; kk < BK; kk++) {
            float4 a0 = *reinterpret_cast<const float4*>(&As[kk][ty * TM]);
            float4 a1 = *reinterpret_cast<const float4*>(&As[kk][ty * TM + 4]);
            float4 bv = *reinterpret_cast<const float4*>(&Bs[kk][tx * TN]);
            float a[TM] = {a0.x, a0.y, a0.z, a0.w, a1.x, a1.y, a1.z, a1.w};
            float bcol[TN] = {bv.x, bv.y, bv.z, bv.w};
            #pragma unroll
            for (int i = 0; i < TM; i++)
                #pragma unroll
                for (int j = 0; j < TN; j++)
                    acc[i][j] += a[i] * bcol[j];
        }
        __syncthreads();
    }

    float bb[TN];
    #pragma unroll
    for (int j = 0; j < TN; j++) {
        int n = block_n + tx * TN + j;
        float bsum = b1[n];
        if (b2) bsum += b2[n];
        bb[j] = bsum;
    }
    #pragma unroll
    for (int i = 0; i < TM; i++) {
        int m = block_m + ty * TM + i;
        float r[TN];
        #pragma unroll
        for (int j = 0; j < TN; j++) {
            float x = acc[i][j] + bb[j];
            if (act == 1) x = tanhf(x);
            r[j] = x;
        }
        *reinterpret_cast<float4*>(&C[(size_t)m * N + block_n + tx * TN]) =
            make_float4(r[0], r[1], r[2], r[3]);
    }
}

// ================= L1: copy slice 1 + all 512 gates tiles ===================
__global__ void __launch_bounds__(256, 3)
mega1_kernel(const float* __restrict__ ch,
             const float* __restrict__ sh,
             const float* __restrict__ sc,
             const int* __restrict__ pos,
             const float* __restrict__ W_ih_r, const float* __restrict__ W_hh_r,
             const float* __restrict__ b_ih_r, const float* __restrict__ b_hh_r,
             const float* __restrict__ W_ih_l,
             const float* __restrict__ b_ih_l, const float* __restrict__ b_hh_l,
             float4* __restrict__ cdh, float4* __restrict__ cdc,
             size_t n4, size_t c0, size_t c1)
{
    __shared__ __align__(16) float As[BK][BM];
    __shared__ __align__(16) float Bs[BK][BN];
    __shared__ int pos_s[BM];

    int bid = blockIdx.x;
    if (bid < NCPY) {
        copy_role(bid, c0, c1, n4, (const float4*)sh, (const float4*)sc, cdh, cdc);
        return;
    }
    int w = bid - NCPY;   // 0..295
    for (int t = w; t < 512; t += 296) {
        if (t < 256) {
            // gemm_r: [char | h@pos] @ [W_ih_r ; W_hh_r]^T, K=1024
            int by = t >> 5, bx = t & 31;    // 8 x 32 tiles, N=2048
            gemm_tile(by * BM, bx * BN, 1, ch, sh, pos,
                      W_ih_r, W_hh_r, IDIM, IDIM + HDIM,
                      b_ih_r, b_hh_r, g_gates_r, G4, 0, As, Bs, pos_s);
        } else {
            // gemm_l: char @ W_ih_l^T, K=512
            int tl = t - 256;
            int by = tl >> 5, bx = tl & 31;
            gemm_tile(by * BM, bx * BN, 0, ch, nullptr, nullptr,
                      W_ih_l, nullptr, IDIM, IDIM,
                      b_ih_l, b_hh_l, g_gates_l, G4, 0, As, Bs, pos_s);
        }
    }
}

// ================= L2: copy slice 2 + LSTM elementwise ======================
__global__ void __launch_bounds__(256, 3)
mega2_kernel(const float* __restrict__ sh,
             const float* __restrict__ sc,
             const int* __restrict__ pos,
             float4* __restrict__ cdh, float4* __restrict__ cdc,
             size_t n4, size_t c0, size_t c1)
{
    int bid = blockIdx.x;
    if (bid < NCPY) {
        copy_role(bid, c0, c1, n4, (const float4*)sh, (const float4*)sc, cdh, cdc);
        return;
    }
    int nwork = gridDim.x - NCPY;
    int stride = nwork * 256;
    for (int idx = (bid - NCPY) * 256 + threadIdx.x; idx < BDIM * HDIM;
         idx += stride) {
        int b = idx / HDIM;
        int j = idx - b * HDIM;

        const float* gr = g_gates_r + (size_t)b * G4;
        const float* gl = g_gates_l + (size_t)b * G4;

        float ig = gr[j];
        float fg = gr[HDIM + j];
        float gg = gr[2 * HDIM + j];
        float og = gr[3 * HDIM + j];

        int p = pos[b];
        float cprev = sc[((size_t)b * SDIM + p) * HDIM + j];
        float cr = sigf(fg) * cprev + sigf(ig) * tanhf(gg);
        float hr = sigf(og) * tanhf(cr);

        float cl = sigf(gl[j]) * tanhf(gl[2 * HDIM + j]);
        float hl = sigf(gl[3 * HDIM + j]) * tanhf(cl);

        g_hlcat[(size_t)b * (2 * HDIM) + j]        = hr;
        g_hlcat[(size_t)b * (2 * HDIM) + HDIM + j] = hl;
        g_hr[idx] = hr;
        g_cr[idx] = cr;
    }
}

// ================= L3: copy slice 3 + compose tiles =========================
__global__ void __launch_bounds__(256, 3)
mega3_kernel(const float* __restrict__ sh,
             const float* __restrict__ sc,
             const float* __restrict__ W_comp, const float* __restrict__ b_comp,
             float* __restrict__ out_sub,
             float4* __restrict__ cdh, float4* __restrict__ cdc,
             size_t n4, size_t c0, size_t c1)
{
    __shared__ __align__(16) float As[BK][BM];
    __shared__ __align__(16) float Bs[BK][BN];
    __shared__ int pos_s[BM];

    int bid = blockIdx.x;
    if (bid < NCPY) {
        copy_role(bid, c0, c1, n4, (const float4*)sh, (const float4*)sc, cdh, cdc);
        return;
    }
    int t = bid - NCPY;   // 0..63: 8 m-tiles x 8 n-tiles, N=512
    int by = t >> 3, bx = t & 7;
    gemm_tile(by * BM, bx * BN, 0, g_hlcat, nullptr, nullptr,
              W_comp, nullptr, 2 * HDIM, 2 * HDIM,
              b_comp, nullptr, out_sub, HDIM, 1, As, Bs, pos_s);
}

// ================= L4: scatter h_r/c_r at pos+1 =============================
__global__ void scatter_kernel(const int* __restrict__ pos,
                               float4* __restrict__ out_h,
                               float4* __restrict__ out_c) {
    int idx = blockIdx.x * blockDim.x + threadIdx.x;   // over B*H/4
    if (idx >= BDIM * (HDIM / 4)) return;
    int b = idx / (HDIM / 4);
    int q = idx - b * (HDIM / 4);
    const float4* hr = (const float4*)g_hr;
    const float4* cr = (const float4*)g_cr;
    int p = pos[b] + 1;
    size_t off = ((size_t)b * SDIM + p) * (HDIM / 4) + q;
    out_h[off] = hr[(size_t)b * (HDIM / 4) + q];
    out_c[off] = cr[(size_t)b * (HDIM / 4) + q];
}

// ---------------------------------------------------------------------------
extern "C" void kernel_launch(void* const* d_in, const int* in_sizes, int n_in,
                              void* d_out, int out_size) {
    const float* ch     = (const float*)d_in[0];
    const float* sh     = (const float*)d_in[1];
    const float* sc     = (const float*)d_in[2];
    const int*   pos    = (const int*)d_in[3];
    const float* W_ih_r = (const float*)d_in[4];
    const float* W_hh_r = (const float*)d_in[5];
    const float* b_ih_r = (const float*)d_in[6];
    const float* b_hh_r = (const float*)d_in[7];
    const float* W_ih_l = (const float*)d_in[8];
    const float* W_hh_l = (const float*)d_in[9];   (void)W_hh_l;  // h=0, unused
    const float* b_ih_l = (const float*)d_in[10];
    const float* b_hh_l = (const float*)d_in[11];
    const float* W_comp = (const float*)d_in[12];
    const float* b_comp = (const float*)d_in[13];

    float* out      = (float*)d_out;
    float* out_sub  = out;                                    // (B, H)
    float* out_h    = out + (size_t)BDIM * HDIM;              // (B, S, H)
    float* out_c    = out_h + (size_t)BDIM * SDIM * HDIM;     // (B, S, H)

    const size_t n4 = (size_t)BDIM * SDIM * HDIM / 4;   // 33,816,576
    const size_t U  = 2 * n4;                           // 67,633,152 units
    float4* cdh = (float4*)out_h;
    float4* cdc = (float4*)out_c;

    // copy slice boundaries (unified float4-unit space), derived from U
    const size_t s1 = (U * 47) / 100;    // ~47%: hidden under gates GEMMs
    const size_t s2 = s1 + (U * 9) / 100;//  ~9%: hidden under LSTM elem
    // remainder (~44%) under compose tiles

    // L1: copy slice1 + gates_r (inline gather) + gates_l
    mega1_kernel<<<NCPY + 296, 256>>>(ch, sh, sc, pos,
                                      W_ih_r, W_hh_r, b_ih_r, b_hh_r,
                                      W_ih_l, b_ih_l, b_hh_l,
                                      cdh, cdc, n4, 0, s1);
    // L2: copy slice2 + LSTM elementwise
    mega2_kernel<<<NCPY + 256, 256>>>(sh, sc, pos, cdh, cdc, n4, s1, s2);
    // L3: copy slice3 + compose (tanh) -> out_sub
    mega3_kernel<<<NCPY + 64, 256>>>(sh, sc, W_comp, b_comp, out_sub,
                                     cdh, cdc, n4, s2, U);
    // L4: scatter (h_r, c_r) at pos+1
    {
        int total = BDIM * (HDIM / 4);
        scatter_kernel<<<(total + 255) / 256, 256>>>(pos, (float4*)out_h,
                                                     (float4*)out_c);
    }
}